// round 14
// baseline (speedup 1.0000x reference)
#include <cuda_runtime.h>
#include <cuda_bf16.h>
#include <cstdint>

#define B_ 64
#define T_ 512
#define E_ 512
#define H_ 512
#define O_ 512
#define BH_ (B_ * H_)
#define M_ (B_ * T_)
#define HSTR 520  // halfs per h row in recurrence SMEM

// Scratch (device globals — only ever dereferenced from device code)
__device__ float g_A[(size_t)T_ * BH_];                  // [t][b][j] x@W1x+b1
__device__ __nv_bfloat16 g_Ax_hi[(size_t)M_ * 512];      // [m][k] split x
__device__ __nv_bfloat16 g_Ax_lo[(size_t)M_ * 512];
__device__ __nv_bfloat16 g_Hh_hi[(size_t)T_ * BH_];      // [t][b][j] split h_t
__device__ __nv_bfloat16 g_Hh_lo[(size_t)T_ * BH_];
__device__ __nv_bfloat16 g_W1t_hi[512 * 512];            // [n][k] W1x^T
__device__ __nv_bfloat16 g_W1t_lo[512 * 512];
__device__ __nv_bfloat16 g_W2t_hi[512 * 1024];           // [n][k] W2^T
__device__ __nv_bfloat16 g_W2t_lo[512 * 1024];

__device__ __forceinline__ uint32_t smem_u32(const void* p) {
    uint32_t a;
    asm("{ .reg .u64 t; cvta.to.shared.u64 t, %1; cvt.u32.u64 %0, t; }"
        : "=r"(a) : "l"(p));
    return a;
}
__device__ __forceinline__ void cp16(uint32_t dst, const void* src) {
    asm volatile("cp.async.cg.shared.global [%0], [%1], 16;" :: "r"(dst), "l"(src));
}
__device__ __forceinline__ void ldmatrix_x4(uint32_t& a0, uint32_t& a1,
                                            uint32_t& a2, uint32_t& a3,
                                            uint32_t addr) {
    asm volatile("ldmatrix.sync.aligned.m8n8.x4.shared.b16 {%0,%1,%2,%3}, [%4];"
                 : "=r"(a0), "=r"(a1), "=r"(a2), "=r"(a3) : "r"(addr));
}
__device__ __forceinline__ void mma16816(float* c, uint32_t a0, uint32_t a1,
                                         uint32_t a2, uint32_t a3,
                                         uint32_t b0, uint32_t b1) {
    asm volatile(
        "mma.sync.aligned.m16n8k16.row.col.f32.bf16.bf16.f32 "
        "{%0,%1,%2,%3}, {%4,%5,%6,%7}, {%8,%9}, {%0,%1,%2,%3};"
        : "+f"(c[0]), "+f"(c[1]), "+f"(c[2]), "+f"(c[3])
        : "r"(a0), "r"(a1), "r"(a2), "r"(a3), "r"(b0), "r"(b1));
}
__device__ __forceinline__ uint32_t packbf2(float lo, float hi) {
    __nv_bfloat162 p = __floats2bfloat162_rn(lo, hi);
    return *(uint32_t*)&p;
}
__device__ __forceinline__ uint32_t lobits(float2 v, uint32_t hiw) {
    __nv_bfloat162 hp = *(__nv_bfloat162*)&hiw;
    return packbf2(v.x - __bfloat162float(hp.x), v.y - __bfloat162float(hp.y));
}
__device__ __forceinline__ uint32_t mapa_u32(uint32_t addr, uint32_t rank) {
    uint32_t r;
    asm("mapa.shared::cluster.u32 %0, %1, %2;" : "=r"(r) : "r"(addr), "r"(rank));
    return r;
}
__device__ __forceinline__ void st_cluster_u32(uint32_t addr, uint32_t v) {
    asm volatile("st.shared::cluster.u32 [%0], %1;" :: "r"(addr), "r"(v) : "memory");
}
#define CLUSTER_ARRIVE() asm volatile("barrier.cluster.arrive.aligned;" ::: "memory")
#define CLUSTER_WAIT()   asm volatile("barrier.cluster.wait.aligned;" ::: "memory")
#define CLUSTER_SYNC() do { CLUSTER_ARRIVE(); CLUSTER_WAIT(); } while (0)
__device__ __forceinline__ float sigmoidf_(float x) {
    return __fdividef(1.0f, 1.0f + __expf(-x));
}

// ---------------------------------------------------------------------------
__global__ void init_kernel() {
    int i = blockIdx.x * blockDim.x + threadIdx.x;  // 32768
    if (i < BH_ / 2) {
        ((uint32_t*)g_Hh_hi)[i] = 0u;
        ((uint32_t*)g_Hh_lo)[i] = 0u;
    }
}

// ---------------------------------------------------------------------------
__global__ __launch_bounds__(256) void split_x_kernel(const float* __restrict__ x) {
    int idx = blockIdx.x * blockDim.x + threadIdx.x;
    int base = idx * 4;
    float4 v = *(const float4*)&x[base];
    __nv_bfloat16 h0 = __float2bfloat16(v.x), h1 = __float2bfloat16(v.y);
    __nv_bfloat16 h2 = __float2bfloat16(v.z), h3 = __float2bfloat16(v.w);
    __nv_bfloat162 hp0, hp1;
    hp0.x = h0; hp0.y = h1; hp1.x = h2; hp1.y = h3;
    uint2 hiv, lov;
    hiv.x = *(uint32_t*)&hp0;
    hiv.y = *(uint32_t*)&hp1;
    lov.x = packbf2(v.x - __bfloat162float(h0), v.y - __bfloat162float(h1));
    lov.y = packbf2(v.z - __bfloat162float(h2), v.w - __bfloat162float(h3));
    *(uint2*)&g_Ax_hi[base] = hiv;
    *(uint2*)&g_Ax_lo[base] = lov;
}

// ---------------------------------------------------------------------------
__global__ __launch_bounds__(256) void split_w_kernel(
    const float* __restrict__ W1, const float* __restrict__ W2) {
    int idx = blockIdx.x * blockDim.x + threadIdx.x;  // 786432
    if (idx < 512 * 512) {
        int k = idx & 511;
        int n = idx >> 9;
        float v = W1[(size_t)k * H_ + n];
        __nv_bfloat16 h = __float2bfloat16(v);
        g_W1t_hi[(size_t)n * 512 + k] = h;
        g_W1t_lo[(size_t)n * 512 + k] = __float2bfloat16(v - __bfloat162float(h));
    } else {
        int i2 = idx - 512 * 512;
        int k = i2 & 1023;
        int n = i2 >> 10;
        float v = W2[(size_t)k * O_ + n];
        __nv_bfloat16 h = __float2bfloat16(v);
        g_W2t_hi[(size_t)n * 1024 + k] = h;
        g_W2t_lo[(size_t)n * 1024 + k] = __float2bfloat16(v - __bfloat162float(h));
    }
}

// ---------------------------------------------------------------------------
// hgemm3 (R9-proven): bf16x3 split HMMA GEMM
// ---------------------------------------------------------------------------
#define GP 72
#define SA_H 0
#define SA_L (128 * GP)
#define SB_H (256 * GP)
#define SB_L (256 * GP + 64 * GP)
#define STG_HALFS (256 * GP + 128 * GP)

__global__ __launch_bounds__(256) void hgemm3(
    const float* __restrict__ bias, float* __restrict__ Cout, int K, int pre) {
    extern __shared__ __align__(16) __nv_bfloat16 sm[];
    const int tid = threadIdx.x;
    const int wid = tid >> 5;
    const int lane = tid & 31;
    const int n0 = blockIdx.x * 64;
    const int m0 = blockIdx.y * 128;
    const uint32_t smb = smem_u32(sm);

    const __nv_bfloat16* __restrict__ Bthi = pre ? g_W1t_hi : g_W2t_hi;
    const __nv_bfloat16* __restrict__ Btlo = pre ? g_W1t_lo : g_W2t_lo;
    float* __restrict__ C = pre ? g_A : Cout;

    const int NC = K >> 6;

    auto load_stage = [&](int kc, int stg) {
        const int k0 = kc << 6;
        const uint32_t sb = smb + (uint32_t)stg * (STG_HALFS * 2);
        const bool hsrc = (k0 >= 512);
#pragma unroll
        for (int i = 0; i < 8; i++) {
            int idx = tid + i * 256;
            int var = idx >> 10;
            int row = (idx >> 3) & 127;
            int c = idx & 7;
            const int m = m0 + row;
            const __nv_bfloat16* src;
            if (!hsrc) {
                src = (var ? g_Ax_lo : g_Ax_hi) + (size_t)m * 512 + k0 + c * 8;
            } else {
                const int tt = m & 511;
                const int bb = m >> 9;
                src = (var ? g_Hh_lo : g_Hh_hi) +
                      (size_t)tt * BH_ + (size_t)bb * 512 + (k0 - 512) + c * 8;
            }
            uint32_t dst = sb + (uint32_t)(var ? SA_L : SA_H) * 2 +
                           (uint32_t)row * (GP * 2) + c * 16;
            cp16(dst, src);
        }
#pragma unroll
        for (int i = 0; i < 4; i++) {
            int idx = tid + i * 256;
            int var = idx >> 9;
            int row = (idx >> 3) & 63;
            int c = idx & 7;
            const __nv_bfloat16* src =
                (var ? Btlo : Bthi) + (size_t)(n0 + row) * K + k0 + c * 8;
            uint32_t dst = sb + (uint32_t)(var ? SB_L : SB_H) * 2 +
                           (uint32_t)row * (GP * 2) + c * 16;
            cp16(dst, src);
        }
        asm volatile("cp.async.commit_group;" ::: "memory");
    };

    const int m0w = (wid >> 1) * 32;
    const int n0w = (wid & 1) * 32;
    const int g = lane >> 2;
    const int t4 = lane & 3;

    const int lrowA = (lane & 7) + ((lane >> 3) & 1) * 8;
    const uint32_t offA = (uint32_t)(m0w + lrowA) * (GP * 2) + (lane >> 4) * 16;
    const int rowB = (lane & 7);
    const int n8sel = (lane >> 4) & 1;
    const uint32_t khB = ((lane >> 3) & 1) * 16;
    const uint32_t offB = (uint32_t)(n0w + n8sel * 8 + rowB) * (GP * 2) + khB;

    float acc[2][4][4];
#pragma unroll
    for (int a = 0; a < 2; a++)
#pragma unroll
        for (int b = 0; b < 4; b++)
#pragma unroll
            for (int c = 0; c < 4; c++) acc[a][b][c] = 0.f;

    load_stage(0, 0);
    for (int kc = 0; kc < NC; kc++) {
        if (kc + 1 < NC) {
            load_stage(kc + 1, (kc + 1) & 1);
            asm volatile("cp.async.wait_group 1;" ::: "memory");
        } else {
            asm volatile("cp.async.wait_group 0;" ::: "memory");
        }
        __syncthreads();

        const uint32_t sb = smb + (uint32_t)(kc & 1) * (STG_HALFS * 2);
        const uint32_t aH = sb + SA_H * 2 + offA;
        const uint32_t aL = sb + SA_L * 2 + offA;
        const uint32_t bH = sb + SB_H * 2 + offB;
        const uint32_t bL = sb + SB_L * 2 + offB;

#pragma unroll
        for (int ks = 0; ks < 4; ks++) {
            uint32_t ah0[4], ah1[4], al0[4], al1[4];
            ldmatrix_x4(ah0[0], ah0[1], ah0[2], ah0[3], aH + ks * 32);
            ldmatrix_x4(ah1[0], ah1[1], ah1[2], ah1[3], aH + 16 * (GP * 2) + ks * 32);
            ldmatrix_x4(al0[0], al0[1], al0[2], al0[3], aL + ks * 32);
            ldmatrix_x4(al1[0], al1[1], al1[2], al1[3], aL + 16 * (GP * 2) + ks * 32);
            uint32_t bh[8], bl[8];
            ldmatrix_x4(bh[0], bh[1], bh[2], bh[3], bH + ks * 32);
            ldmatrix_x4(bh[4], bh[5], bh[6], bh[7], bH + 16 * (GP * 2) + ks * 32);
            ldmatrix_x4(bl[0], bl[1], bl[2], bl[3], bL + ks * 32);
            ldmatrix_x4(bl[4], bl[5], bl[6], bl[7], bL + 16 * (GP * 2) + ks * 32);
#pragma unroll
            for (int nt = 0; nt < 4; nt++) {
                uint32_t b0h = bh[nt * 2], b1h = bh[nt * 2 + 1];
                uint32_t b0l = bl[nt * 2], b1l = bl[nt * 2 + 1];
                mma16816(acc[0][nt], ah0[0], ah0[1], ah0[2], ah0[3], b0h, b1h);
                mma16816(acc[0][nt], ah0[0], ah0[1], ah0[2], ah0[3], b0l, b1l);
                mma16816(acc[0][nt], al0[0], al0[1], al0[2], al0[3], b0h, b1h);
                mma16816(acc[1][nt], ah1[0], ah1[1], ah1[2], ah1[3], b0h, b1h);
                mma16816(acc[1][nt], ah1[0], ah1[1], ah1[2], ah1[3], b0l, b1l);
                mma16816(acc[1][nt], al1[0], al1[1], al1[2], al1[3], b0h, b1h);
            }
        }
        __syncthreads();
    }

#pragma unroll
    for (int mt = 0; mt < 2; mt++) {
#pragma unroll
        for (int nt = 0; nt < 4; nt++) {
            const int n = n0 + n0w + nt * 8 + 2 * t4;
            float2 bi = *(const float2*)&bias[n];
#pragma unroll
            for (int rr = 0; rr < 2; rr++) {
                const int m = m0 + m0w + mt * 16 + g + rr * 8;
                float2 v;
                v.x = acc[mt][nt][rr * 2 + 0] + bi.x;
                v.y = acc[mt][nt][rr * 2 + 1] + bi.y;
                if (pre) {
                    int bb = m >> 9;
                    int tt = m & 511;
                    *(float2*)&C[(size_t)tt * BH_ + bb * H_ + n] = v;
                } else {
                    *(float2*)&C[(size_t)m * O_ + n] = v;
                }
            }
        }
    }
}

// ---------------------------------------------------------------------------
// Cluster recurrence: R13 base + software pipeline — own-slice k-steps of the
// NEXT step's mma run in the arrive->wait gap (own h written locally; peers'
// regions disjoint). At t=0 the own-slice partial is exactly 0 (h_0 = 0).
// ---------------------------------------------------------------------------
__global__ __launch_bounds__(256, 1) __cluster_dims__(4, 1, 1)
void recurrence_cluster(const float* __restrict__ W1, float* __restrict__ hid_out) {
    __shared__ __align__(16) uint16_t hsm[2][16 * HSTR];

    const int tid = threadIdx.x;
    const int wid = tid >> 5;
    const int lane = tid & 31;
    uint32_t crank;
    asm("mov.u32 %0, %%cluster_ctarank;" : "=r"(crank));
    const int bbase = (blockIdx.x >> 2) * 16;
    const int g = lane >> 2;
    const int t4 = lane & 3;
    const int n0w = wid * 16;
    const int sown = (int)crank * 8;  // own-slice k-steps [sown, sown+8)

    const float* Wh = W1 + (size_t)E_ * H_;
    uint32_t bfrag[32][2][2];
    {
        const int nb = (int)crank * 128 + n0w + g;
#pragma unroll
        for (int s = 0; s < 32; s++) {
#pragma unroll
            for (int nt = 0; nt < 2; nt++) {
                const int n = nb + nt * 8;
                const int k0 = 16 * s + 2 * t4;
                float f00 = Wh[(size_t)k0 * H_ + n];
                float f01 = Wh[(size_t)(k0 + 1) * H_ + n];
                float f10 = Wh[(size_t)(k0 + 8) * H_ + n];
                float f11 = Wh[(size_t)(k0 + 9) * H_ + n];
                bfrag[s][nt][0] = packbf2(f00, f01);
                bfrag[s][nt][1] = packbf2(f10, f11);
            }
        }
    }

    for (int i = tid; i < (int)(2 * 16 * HSTR * 2 / 16); i += 256)
        ((uint4*)hsm)[i] = make_uint4(0u, 0u, 0u, 0u);
    __syncthreads();
    CLUSTER_SYNC();

    const uint32_t hb0 = smem_u32(&hsm[0][0]);
    const uint32_t hb1 = smem_u32(&hsm[1][0]);
    uint32_t rb[4][2];
#pragma unroll
    for (int r = 0; r < 4; r++) {
        rb[r][0] = mapa_u32(hb0, (uint32_t)r);
        rb[r][1] = mapa_u32(hb1, (uint32_t)r);
    }

    const int lrow = (lane & 7) + ((lane >> 3) & 1) * 8;
    const uint32_t lmoff = (uint32_t)lrow * (HSTR * 2) + (lane >> 4) * 16;
    const uint32_t lm0 = hb0 + lmoff;
    const uint32_t lm1 = hb1 + lmoff;

    const int jg0 = (int)crank * 128 + n0w + 2 * t4;
    const int jg1 = jg0 + 8;
    const int br0 = bbase + g;
    const int br1 = br0 + 8;

    const uint32_t f00 = (uint32_t)g * (HSTR * 2) + (uint32_t)jg0 * 2;
    const uint32_t f01 = (uint32_t)(g + 8) * (HSTR * 2) + (uint32_t)jg0 * 2;
    const uint32_t f10 = (uint32_t)g * (HSTR * 2) + (uint32_t)jg1 * 2;
    const uint32_t f11 = (uint32_t)(g + 8) * (HSTR * 2) + (uint32_t)jg1 * 2;

    // prefetch g_A for t=0
    float2 pa00 = *(const float2*)&g_A[(size_t)br0 * H_ + jg0];
    float2 pa01 = *(const float2*)&g_A[(size_t)br1 * H_ + jg0];
    float2 pa10 = *(const float2*)&g_A[(size_t)br0 * H_ + jg1];
    float2 pa11 = *(const float2*)&g_A[(size_t)br1 * H_ + jg1];

    // pipelined partial accumulators (own k-steps of current step's mma);
    // zero for t=0 since h_0 = 0.
    float c0p[4] = {0.f, 0.f, 0.f, 0.f};
    float c1p[4] = {0.f, 0.f, 0.f, 0.f};

    for (int t = 0; t < T_; t++) {
        const uint32_t lm = (t & 1) ? lm1 : lm0;
        float c0[4] = {c0p[0], c0p[1], c0p[2], c0p[3]};
        float c1[4] = {c1p[0], c1p[1], c1p[2], c1p[3]};
        // foreign 24 k-steps (own 8 already accumulated in the previous gap)
#pragma unroll
        for (int s = 0; s < 32; s++) {
            if ((s >> 3) == (int)crank) continue;  // warp-uniform branch
            uint32_t a0, a1, a2, a3;
            ldmatrix_x4(a0, a1, a2, a3, lm + s * 32);
            mma16816(c0, a0, a1, a2, a3, bfrag[s][0][0], bfrag[s][0][1]);
            mma16816(c1, a0, a1, a2, a3, bfrag[s][1][0], bfrag[s][1][1]);
        }

        float2 o00, o01, o10, o11;
        o00.x = sigmoidf_(pa00.x + c0[0]);
        o00.y = sigmoidf_(pa00.y + c0[1]);
        o01.x = sigmoidf_(pa01.x + c0[2]);
        o01.y = sigmoidf_(pa01.y + c0[3]);
        o10.x = sigmoidf_(pa10.x + c1[0]);
        o10.y = sigmoidf_(pa10.y + c1[1]);
        o11.x = sigmoidf_(pa11.x + c1[2]);
        o11.y = sigmoidf_(pa11.y + c1[3]);

        if (t < T_ - 1) {
            const uint32_t u00 = packbf2(o00.x, o00.y);
            const uint32_t u01 = packbf2(o01.x, o01.y);
            const uint32_t u10 = packbf2(o10.x, o10.y);
            const uint32_t u11 = packbf2(o11.x, o11.y);

            const int wb = 1 - (t & 1);
            // own rank: plain STS
            {
                char* lb = (char*)&hsm[wb][0];
                *(uint32_t*)(lb + f00) = u00;
                *(uint32_t*)(lb + f01) = u01;
                *(uint32_t*)(lb + f10) = u10;
                *(uint32_t*)(lb + f11) = u11;
            }
            // peers: DSMEM push
#pragma unroll
            for (int r = 0; r < 4; r++) {
                if (r == (int)crank) continue;
                const uint32_t tb = rb[r][wb];
                st_cluster_u32(tb + f00, u00);
                st_cluster_u32(tb + f01, u01);
                st_cluster_u32(tb + f10, u10);
                st_cluster_u32(tb + f11, u11);
            }
            CLUSTER_ARRIVE();   // release: prior cluster stores visible at wait
            __syncthreads();    // own STS visible intra-CTA for gap mma

            // ---- gap work (overlaps barrier drain/skew) ----
            // (1) next step's mma over OWN 8 k-steps (local data only)
            const uint32_t lmn = (wb ? lm1 : lm0);
            c0p[0] = c0p[1] = c0p[2] = c0p[3] = 0.f;
            c1p[0] = c1p[1] = c1p[2] = c1p[3] = 0.f;
#pragma unroll
            for (int s8 = 0; s8 < 8; s8++) {
                const int s = sown + s8;
                uint32_t a0, a1, a2, a3;
                ldmatrix_x4(a0, a1, a2, a3, lmn + s * 32);
                mma16816(c0p, a0, a1, a2, a3, bfrag[s][0][0], bfrag[s][0][1]);
                mma16816(c1p, a0, a1, a2, a3, bfrag[s][1][0], bfrag[s][1][1]);
            }
            // (2) prefetch g_A for step t+1
            const size_t baseA1 = (size_t)(t + 1) * BH_;
            pa00 = *(const float2*)&g_A[baseA1 + (size_t)br0 * H_ + jg0];
            pa01 = *(const float2*)&g_A[baseA1 + (size_t)br1 * H_ + jg0];
            pa10 = *(const float2*)&g_A[baseA1 + (size_t)br0 * H_ + jg1];
            pa11 = *(const float2*)&g_A[baseA1 + (size_t)br1 * H_ + jg1];
            // (3) lo splits + GMEM h stores
            const size_t baseH = (size_t)(t + 1) * BH_;
            *(uint32_t*)&g_Hh_hi[baseH + (size_t)br0 * H_ + jg0] = u00;
            *(uint32_t*)&g_Hh_hi[baseH + (size_t)br1 * H_ + jg0] = u01;
            *(uint32_t*)&g_Hh_hi[baseH + (size_t)br0 * H_ + jg1] = u10;
            *(uint32_t*)&g_Hh_hi[baseH + (size_t)br1 * H_ + jg1] = u11;
            *(uint32_t*)&g_Hh_lo[baseH + (size_t)br0 * H_ + jg0] = lobits(o00, u00);
            *(uint32_t*)&g_Hh_lo[baseH + (size_t)br1 * H_ + jg0] = lobits(o01, u01);
            *(uint32_t*)&g_Hh_lo[baseH + (size_t)br0 * H_ + jg1] = lobits(o10, u10);
            *(uint32_t*)&g_Hh_lo[baseH + (size_t)br1 * H_ + jg1] = lobits(o11, u11);

            CLUSTER_WAIT();     // acquire: all peers' pushes visible
        } else if (hid_out != nullptr) {
            *(float2*)&hid_out[br0 * H_ + jg0] = o00;
            *(float2*)&hid_out[br1 * H_ + jg0] = o01;
            *(float2*)&hid_out[br0 * H_ + jg1] = o10;
            *(float2*)&hid_out[br1 * H_ + jg1] = o11;
        }
    }
}

// ---------------------------------------------------------------------------
extern "C" void kernel_launch(void* const* d_in, const int* in_sizes, int n_in,
                              void* d_out, int out_size) {
    const float* x = (const float*)d_in[0];
    const float* W1 = (const float*)d_in[1];
    const float* b1 = (const float*)d_in[2];
    const float* W2 = (const float*)d_in[3];
    const float* b2 = (const float*)d_in[4];
    float* out = (float*)d_out;

    float* hid_out = nullptr;
    if (out_size >= B_ * T_ * O_ + B_ * H_)
        hid_out = out + (size_t)B_ * T_ * O_;

    const int gemm_smem = STG_HALFS * 2 * 2;  // 110592 B
    static int attr_done = 0;
    if (!attr_done) {
        cudaFuncSetAttribute(hgemm3, cudaFuncAttributeMaxDynamicSharedMemorySize,
                             gemm_smem);
        attr_done = 1;
    }

    init_kernel<<<128, 256>>>();
    split_x_kernel<<<16384, 256>>>(x);
    split_w_kernel<<<3072, 256>>>(W1, W2);
    hgemm3<<<dim3(8, 256), 256, gemm_smem>>>(b1, nullptr, 512, 1);   // pre
    recurrence_cluster<<<16, 256>>>(W1, hid_out);
    hgemm3<<<dim3(8, 256), 256, gemm_smem>>>(b2, out, 1024, 0);      // post
}

// round 15
// speedup vs baseline: 1.1256x; 1.1256x over previous
#include <cuda_runtime.h>
#include <cuda_bf16.h>
#include <cstdint>

#define B_ 64
#define T_ 512
#define E_ 512
#define H_ 512
#define O_ 512
#define BH_ (B_ * H_)
#define M_ (B_ * T_)
#define HSTR 520  // halfs per h row in recurrence SMEM

// Scratch (device globals — only ever dereferenced from device code)
__device__ float g_A[(size_t)T_ * BH_];                  // [t][b][j] x@W1x+b1
__device__ __nv_bfloat16 g_Ax_hi[(size_t)M_ * 512];      // [m][k] split x
__device__ __nv_bfloat16 g_Ax_lo[(size_t)M_ * 512];
__device__ __nv_bfloat16 g_Hh_hi[(size_t)T_ * BH_];      // [t][b][j] split h_t
__device__ __nv_bfloat16 g_Hh_lo[(size_t)T_ * BH_];
__device__ __nv_bfloat16 g_W1t_hi[512 * 512];            // [n][k] W1x^T
__device__ __nv_bfloat16 g_W1t_lo[512 * 512];
__device__ __nv_bfloat16 g_W2t_hi[512 * 1024];           // [n][k] W2^T
__device__ __nv_bfloat16 g_W2t_lo[512 * 1024];

__device__ __forceinline__ uint32_t smem_u32(const void* p) {
    uint32_t a;
    asm("{ .reg .u64 t; cvta.to.shared.u64 t, %1; cvt.u32.u64 %0, t; }"
        : "=r"(a) : "l"(p));
    return a;
}
__device__ __forceinline__ void cp16(uint32_t dst, const void* src) {
    asm volatile("cp.async.cg.shared.global [%0], [%1], 16;" :: "r"(dst), "l"(src));
}
__device__ __forceinline__ void ldmatrix_x4(uint32_t& a0, uint32_t& a1,
                                            uint32_t& a2, uint32_t& a3,
                                            uint32_t addr) {
    asm volatile("ldmatrix.sync.aligned.m8n8.x4.shared.b16 {%0,%1,%2,%3}, [%4];"
                 : "=r"(a0), "=r"(a1), "=r"(a2), "=r"(a3) : "r"(addr));
}
__device__ __forceinline__ void mma16816(float* c, uint32_t a0, uint32_t a1,
                                         uint32_t a2, uint32_t a3,
                                         uint32_t b0, uint32_t b1) {
    asm volatile(
        "mma.sync.aligned.m16n8k16.row.col.f32.bf16.bf16.f32 "
        "{%0,%1,%2,%3}, {%4,%5,%6,%7}, {%8,%9}, {%0,%1,%2,%3};"
        : "+f"(c[0]), "+f"(c[1]), "+f"(c[2]), "+f"(c[3])
        : "r"(a0), "r"(a1), "r"(a2), "r"(a3), "r"(b0), "r"(b1));
}
__device__ __forceinline__ uint32_t packbf2(float lo, float hi) {
    __nv_bfloat162 p = __floats2bfloat162_rn(lo, hi);
    return *(uint32_t*)&p;
}
__device__ __forceinline__ uint32_t lobits(float2 v, uint32_t hiw) {
    __nv_bfloat162 hp = *(__nv_bfloat162*)&hiw;
    return packbf2(v.x - __bfloat162float(hp.x), v.y - __bfloat162float(hp.y));
}
__device__ __forceinline__ uint32_t mapa_u32(uint32_t addr, uint32_t rank) {
    uint32_t r;
    asm("mapa.shared::cluster.u32 %0, %1, %2;" : "=r"(r) : "r"(addr), "r"(rank));
    return r;
}
__device__ __forceinline__ void st_cluster_u32(uint32_t addr, uint32_t v) {
    asm volatile("st.shared::cluster.u32 [%0], %1;" :: "r"(addr), "r"(v) : "memory");
}
#define CLUSTER_ARRIVE() asm volatile("barrier.cluster.arrive.aligned;" ::: "memory")
#define CLUSTER_WAIT()   asm volatile("barrier.cluster.wait.aligned;" ::: "memory")
#define CLUSTER_SYNC() do { CLUSTER_ARRIVE(); CLUSTER_WAIT(); } while (0)
__device__ __forceinline__ float sigmoidf_(float x) {
    return __fdividef(1.0f, 1.0f + __expf(-x));
}

// ---------------------------------------------------------------------------
__global__ void init_kernel() {
    int i = blockIdx.x * blockDim.x + threadIdx.x;  // 32768
    if (i < BH_ / 2) {
        ((uint32_t*)g_Hh_hi)[i] = 0u;
        ((uint32_t*)g_Hh_lo)[i] = 0u;
    }
}

// ---------------------------------------------------------------------------
__global__ __launch_bounds__(256) void split_x_kernel(const float* __restrict__ x) {
    int idx = blockIdx.x * blockDim.x + threadIdx.x;
    int base = idx * 4;
    float4 v = *(const float4*)&x[base];
    __nv_bfloat16 h0 = __float2bfloat16(v.x), h1 = __float2bfloat16(v.y);
    __nv_bfloat16 h2 = __float2bfloat16(v.z), h3 = __float2bfloat16(v.w);
    __nv_bfloat162 hp0, hp1;
    hp0.x = h0; hp0.y = h1; hp1.x = h2; hp1.y = h3;
    uint2 hiv, lov;
    hiv.x = *(uint32_t*)&hp0;
    hiv.y = *(uint32_t*)&hp1;
    lov.x = packbf2(v.x - __bfloat162float(h0), v.y - __bfloat162float(h1));
    lov.y = packbf2(v.z - __bfloat162float(h2), v.w - __bfloat162float(h3));
    *(uint2*)&g_Ax_hi[base] = hiv;
    *(uint2*)&g_Ax_lo[base] = lov;
}

// ---------------------------------------------------------------------------
__global__ __launch_bounds__(256) void split_w_kernel(
    const float* __restrict__ W1, const float* __restrict__ W2) {
    int idx = blockIdx.x * blockDim.x + threadIdx.x;  // 786432
    if (idx < 512 * 512) {
        int k = idx & 511;
        int n = idx >> 9;
        float v = W1[(size_t)k * H_ + n];
        __nv_bfloat16 h = __float2bfloat16(v);
        g_W1t_hi[(size_t)n * 512 + k] = h;
        g_W1t_lo[(size_t)n * 512 + k] = __float2bfloat16(v - __bfloat162float(h));
    } else {
        int i2 = idx - 512 * 512;
        int k = i2 & 1023;
        int n = i2 >> 10;
        float v = W2[(size_t)k * O_ + n];
        __nv_bfloat16 h = __float2bfloat16(v);
        g_W2t_hi[(size_t)n * 1024 + k] = h;
        g_W2t_lo[(size_t)n * 1024 + k] = __float2bfloat16(v - __bfloat162float(h));
    }
}

// ---------------------------------------------------------------------------
// hgemm3 (R9-proven): bf16x3 split HMMA GEMM
// ---------------------------------------------------------------------------
#define GP 72
#define SA_H 0
#define SA_L (128 * GP)
#define SB_H (256 * GP)
#define SB_L (256 * GP + 64 * GP)
#define STG_HALFS (256 * GP + 128 * GP)

__global__ __launch_bounds__(256) void hgemm3(
    const float* __restrict__ bias, float* __restrict__ Cout, int K, int pre) {
    extern __shared__ __align__(16) __nv_bfloat16 sm[];
    const int tid = threadIdx.x;
    const int wid = tid >> 5;
    const int lane = tid & 31;
    const int n0 = blockIdx.x * 64;
    const int m0 = blockIdx.y * 128;
    const uint32_t smb = smem_u32(sm);

    const __nv_bfloat16* __restrict__ Bthi = pre ? g_W1t_hi : g_W2t_hi;
    const __nv_bfloat16* __restrict__ Btlo = pre ? g_W1t_lo : g_W2t_lo;
    float* __restrict__ C = pre ? g_A : Cout;

    const int NC = K >> 6;

    auto load_stage = [&](int kc, int stg) {
        const int k0 = kc << 6;
        const uint32_t sb = smb + (uint32_t)stg * (STG_HALFS * 2);
        const bool hsrc = (k0 >= 512);
#pragma unroll
        for (int i = 0; i < 8; i++) {
            int idx = tid + i * 256;
            int var = idx >> 10;
            int row = (idx >> 3) & 127;
            int c = idx & 7;
            const int m = m0 + row;
            const __nv_bfloat16* src;
            if (!hsrc) {
                src = (var ? g_Ax_lo : g_Ax_hi) + (size_t)m * 512 + k0 + c * 8;
            } else {
                const int tt = m & 511;
                const int bb = m >> 9;
                src = (var ? g_Hh_lo : g_Hh_hi) +
                      (size_t)tt * BH_ + (size_t)bb * 512 + (k0 - 512) + c * 8;
            }
            uint32_t dst = sb + (uint32_t)(var ? SA_L : SA_H) * 2 +
                           (uint32_t)row * (GP * 2) + c * 16;
            cp16(dst, src);
        }
#pragma unroll
        for (int i = 0; i < 4; i++) {
            int idx = tid + i * 256;
            int var = idx >> 9;
            int row = (idx >> 3) & 63;
            int c = idx & 7;
            const __nv_bfloat16* src =
                (var ? Btlo : Bthi) + (size_t)(n0 + row) * K + k0 + c * 8;
            uint32_t dst = sb + (uint32_t)(var ? SB_L : SB_H) * 2 +
                           (uint32_t)row * (GP * 2) + c * 16;
            cp16(dst, src);
        }
        asm volatile("cp.async.commit_group;" ::: "memory");
    };

    const int m0w = (wid >> 1) * 32;
    const int n0w = (wid & 1) * 32;
    const int g = lane >> 2;
    const int t4 = lane & 3;

    const int lrowA = (lane & 7) + ((lane >> 3) & 1) * 8;
    const uint32_t offA = (uint32_t)(m0w + lrowA) * (GP * 2) + (lane >> 4) * 16;
    const int rowB = (lane & 7);
    const int n8sel = (lane >> 4) & 1;
    const uint32_t khB = ((lane >> 3) & 1) * 16;
    const uint32_t offB = (uint32_t)(n0w + n8sel * 8 + rowB) * (GP * 2) + khB;

    float acc[2][4][4];
#pragma unroll
    for (int a = 0; a < 2; a++)
#pragma unroll
        for (int b = 0; b < 4; b++)
#pragma unroll
            for (int c = 0; c < 4; c++) acc[a][b][c] = 0.f;

    load_stage(0, 0);
    for (int kc = 0; kc < NC; kc++) {
        if (kc + 1 < NC) {
            load_stage(kc + 1, (kc + 1) & 1);
            asm volatile("cp.async.wait_group 1;" ::: "memory");
        } else {
            asm volatile("cp.async.wait_group 0;" ::: "memory");
        }
        __syncthreads();

        const uint32_t sb = smb + (uint32_t)(kc & 1) * (STG_HALFS * 2);
        const uint32_t aH = sb + SA_H * 2 + offA;
        const uint32_t aL = sb + SA_L * 2 + offA;
        const uint32_t bH = sb + SB_H * 2 + offB;
        const uint32_t bL = sb + SB_L * 2 + offB;

#pragma unroll
        for (int ks = 0; ks < 4; ks++) {
            uint32_t ah0[4], ah1[4], al0[4], al1[4];
            ldmatrix_x4(ah0[0], ah0[1], ah0[2], ah0[3], aH + ks * 32);
            ldmatrix_x4(ah1[0], ah1[1], ah1[2], ah1[3], aH + 16 * (GP * 2) + ks * 32);
            ldmatrix_x4(al0[0], al0[1], al0[2], al0[3], aL + ks * 32);
            ldmatrix_x4(al1[0], al1[1], al1[2], al1[3], aL + 16 * (GP * 2) + ks * 32);
            uint32_t bh[8], bl[8];
            ldmatrix_x4(bh[0], bh[1], bh[2], bh[3], bH + ks * 32);
            ldmatrix_x4(bh[4], bh[5], bh[6], bh[7], bH + 16 * (GP * 2) + ks * 32);
            ldmatrix_x4(bl[0], bl[1], bl[2], bl[3], bL + ks * 32);
            ldmatrix_x4(bl[4], bl[5], bl[6], bl[7], bL + 16 * (GP * 2) + ks * 32);
#pragma unroll
            for (int nt = 0; nt < 4; nt++) {
                uint32_t b0h = bh[nt * 2], b1h = bh[nt * 2 + 1];
                uint32_t b0l = bl[nt * 2], b1l = bl[nt * 2 + 1];
                mma16816(acc[0][nt], ah0[0], ah0[1], ah0[2], ah0[3], b0h, b1h);
                mma16816(acc[0][nt], ah0[0], ah0[1], ah0[2], ah0[3], b0l, b1l);
                mma16816(acc[0][nt], al0[0], al0[1], al0[2], al0[3], b0h, b1h);
                mma16816(acc[1][nt], ah1[0], ah1[1], ah1[2], ah1[3], b0h, b1h);
                mma16816(acc[1][nt], ah1[0], ah1[1], ah1[2], ah1[3], b0l, b1l);
                mma16816(acc[1][nt], al1[0], al1[1], al1[2], al1[3], b0h, b1h);
            }
        }
        __syncthreads();
    }

#pragma unroll
    for (int mt = 0; mt < 2; mt++) {
#pragma unroll
        for (int nt = 0; nt < 4; nt++) {
            const int n = n0 + n0w + nt * 8 + 2 * t4;
            float2 bi = *(const float2*)&bias[n];
#pragma unroll
            for (int rr = 0; rr < 2; rr++) {
                const int m = m0 + m0w + mt * 16 + g + rr * 8;
                float2 v;
                v.x = acc[mt][nt][rr * 2 + 0] + bi.x;
                v.y = acc[mt][nt][rr * 2 + 1] + bi.y;
                if (pre) {
                    int bb = m >> 9;
                    int tt = m & 511;
                    *(float2*)&C[(size_t)tt * BH_ + bb * H_ + n] = v;
                } else {
                    *(float2*)&C[(size_t)m * O_ + n] = v;
                }
            }
        }
    }
}

// ---------------------------------------------------------------------------
// Cluster recurrence, k-split warp grid:
//   warp (wj = wid&3, wk = wid>>2): 16 rows x 32 j (4 n8-tiles), k-half wk.
// A-crossbar traffic halves (8 x 8KB vs 8 x 16KB). wk=1 warps reduce via
// padded SMEM; wk=0 warps (one per SMSP) own the epilogue + pushes.
// Exchange/barrier structure identical to R13 (split cluster barrier + gap).
// ---------------------------------------------------------------------------
__global__ __launch_bounds__(256, 1) __cluster_dims__(4, 1, 1)
void recurrence_cluster(const float* __restrict__ W1, float* __restrict__ hid_out) {
    __shared__ __align__(16) uint16_t hsm[2][16 * HSTR];
    __shared__ float redsm[4][32][17];  // [wj][lane][16 vals], pad 17 (no conflicts)

    const int tid = threadIdx.x;
    const int wid = tid >> 5;
    const int lane = tid & 31;
    uint32_t crank;
    asm("mov.u32 %0, %%cluster_ctarank;" : "=r"(crank));
    const int bbase = (blockIdx.x >> 2) * 16;
    const int g = lane >> 2;
    const int t4 = lane & 3;
    const int wj = wid & 3;       // j-group (32 cols)
    const int wk = wid >> 2;      // k-half
    const int n0w = wj * 32;

    // ---- bfrag[16][4][2]: W1h^T, own k-half, 4 n8-tiles ----
    const float* Wh = W1 + (size_t)E_ * H_;
    uint32_t bfrag[16][4][2];
    {
        const int nb = (int)crank * 128 + n0w + g;
#pragma unroll
        for (int s = 0; s < 16; s++) {
            const int k0 = wk * 256 + 16 * s + 2 * t4;
#pragma unroll
            for (int nt = 0; nt < 4; nt++) {
                const int n = nb + nt * 8;
                float f00 = Wh[(size_t)k0 * H_ + n];
                float f01 = Wh[(size_t)(k0 + 1) * H_ + n];
                float f10 = Wh[(size_t)(k0 + 8) * H_ + n];
                float f11 = Wh[(size_t)(k0 + 9) * H_ + n];
                bfrag[s][nt][0] = packbf2(f00, f01);
                bfrag[s][nt][1] = packbf2(f10, f11);
            }
        }
    }

    for (int i = tid; i < (int)(2 * 16 * HSTR * 2 / 16); i += 256)
        ((uint4*)hsm)[i] = make_uint4(0u, 0u, 0u, 0u);
    __syncthreads();
    CLUSTER_SYNC();

    const uint32_t hb0 = smem_u32(&hsm[0][0]);
    const uint32_t hb1 = smem_u32(&hsm[1][0]);
    uint32_t rb[4][2];
#pragma unroll
    for (int r = 0; r < 4; r++) {
        rb[r][0] = mapa_u32(hb0, (uint32_t)r);
        rb[r][1] = mapa_u32(hb1, (uint32_t)r);
    }

    const int lrow = (lane & 7) + ((lane >> 3) & 1) * 8;
    const uint32_t lmoff = (uint32_t)lrow * (HSTR * 2) + (lane >> 4) * 16;
    const uint32_t lm0 = hb0 + lmoff;
    const uint32_t lm1 = hb1 + lmoff;

    const int br0 = bbase + g;
    const int br1 = br0 + 8;
    int jg[4];
    uint32_t foff[4][2];
#pragma unroll
    for (int nt = 0; nt < 4; nt++) {
        jg[nt] = (int)crank * 128 + n0w + nt * 8 + 2 * t4;
        foff[nt][0] = (uint32_t)g * (HSTR * 2) + (uint32_t)jg[nt] * 2;
        foff[nt][1] = (uint32_t)(g + 8) * (HSTR * 2) + (uint32_t)jg[nt] * 2;
    }

    // prefetch g_A for t=0 (only wk=0 needs it)
    float2 pa[4][2];
    if (wk == 0) {
#pragma unroll
        for (int nt = 0; nt < 4; nt++) {
            pa[nt][0] = *(const float2*)&g_A[(size_t)br0 * H_ + jg[nt]];
            pa[nt][1] = *(const float2*)&g_A[(size_t)br1 * H_ + jg[nt]];
        }
    }

    for (int t = 0; t < T_; t++) {
        const uint32_t lm = (t & 1) ? lm1 : lm0;
        float c[4][4];
#pragma unroll
        for (int nt = 0; nt < 4; nt++)
#pragma unroll
            for (int i = 0; i < 4; i++) c[nt][i] = 0.f;
#pragma unroll
        for (int s = 0; s < 16; s++) {
            uint32_t a0, a1, a2, a3;
            ldmatrix_x4(a0, a1, a2, a3, lm + (uint32_t)(wk * 16 + s) * 32);
#pragma unroll
            for (int nt = 0; nt < 4; nt++)
                mma16816(c[nt], a0, a1, a2, a3, bfrag[s][nt][0], bfrag[s][nt][1]);
        }

        // ---- cross-k reduction: wk=1 stores, wk=0 adds ----
        if (wk == 1) {
#pragma unroll
            for (int nt = 0; nt < 4; nt++)
#pragma unroll
                for (int i = 0; i < 4; i++)
                    redsm[wj][lane][nt * 4 + i] = c[nt][i];
        }
        __syncthreads();

        float2 o[4][2];
        if (wk == 0) {
#pragma unroll
            for (int nt = 0; nt < 4; nt++) {
#pragma unroll
                for (int i = 0; i < 4; i++) c[nt][i] += redsm[wj][lane][nt * 4 + i];
                o[nt][0].x = sigmoidf_(pa[nt][0].x + c[nt][0]);
                o[nt][0].y = sigmoidf_(pa[nt][0].y + c[nt][1]);
                o[nt][1].x = sigmoidf_(pa[nt][1].x + c[nt][2]);
                o[nt][1].y = sigmoidf_(pa[nt][1].y + c[nt][3]);
            }
        }

        if (t < T_ - 1) {
            const int wb = 1 - (t & 1);
            uint32_t u[4][2];
            if (wk == 0) {
#pragma unroll
                for (int nt = 0; nt < 4; nt++) {
                    u[nt][0] = packbf2(o[nt][0].x, o[nt][0].y);
                    u[nt][1] = packbf2(o[nt][1].x, o[nt][1].y);
                }
                // own rank: plain STS
                char* lb = (char*)&hsm[wb][0];
#pragma unroll
                for (int nt = 0; nt < 4; nt++) {
                    *(uint32_t*)(lb + foff[nt][0]) = u[nt][0];
                    *(uint32_t*)(lb + foff[nt][1]) = u[nt][1];
                }
                // peers: DSMEM push
#pragma unroll
                for (int r = 0; r < 4; r++) {
                    if (r == (int)crank) continue;
                    const uint32_t tb = rb[r][wb];
#pragma unroll
                    for (int nt = 0; nt < 4; nt++) {
                        st_cluster_u32(tb + foff[nt][0], u[nt][0]);
                        st_cluster_u32(tb + foff[nt][1], u[nt][1]);
                    }
                }
            }
            CLUSTER_ARRIVE();  // release; wk=1 arrives early (absorbs skew)

            if (wk == 0) {
                // ---- gap work (off critical path) ----
                const size_t baseA1 = (size_t)(t + 1) * BH_;
                const size_t baseH = (size_t)(t + 1) * BH_;
#pragma unroll
                for (int nt = 0; nt < 4; nt++) {
                    pa[nt][0] = *(const float2*)&g_A[baseA1 + (size_t)br0 * H_ + jg[nt]];
                    pa[nt][1] = *(const float2*)&g_A[baseA1 + (size_t)br1 * H_ + jg[nt]];
                    *(uint32_t*)&g_Hh_hi[baseH + (size_t)br0 * H_ + jg[nt]] = u[nt][0];
                    *(uint32_t*)&g_Hh_hi[baseH + (size_t)br1 * H_ + jg[nt]] = u[nt][1];
                    *(uint32_t*)&g_Hh_lo[baseH + (size_t)br0 * H_ + jg[nt]] =
                        lobits(o[nt][0], u[nt][0]);
                    *(uint32_t*)&g_Hh_lo[baseH + (size_t)br1 * H_ + jg[nt]] =
                        lobits(o[nt][1], u[nt][1]);
                }
            }
            CLUSTER_WAIT();    // acquire: all pushes visible
        } else if (hid_out != nullptr && wk == 0) {
#pragma unroll
            for (int nt = 0; nt < 4; nt++) {
                *(float2*)&hid_out[br0 * H_ + jg[nt]] = o[nt][0];
                *(float2*)&hid_out[br1 * H_ + jg[nt]] = o[nt][1];
            }
        }
    }
}

// ---------------------------------------------------------------------------
extern "C" void kernel_launch(void* const* d_in, const int* in_sizes, int n_in,
                              void* d_out, int out_size) {
    const float* x = (const float*)d_in[0];
    const float* W1 = (const float*)d_in[1];
    const float* b1 = (const float*)d_in[2];
    const float* W2 = (const float*)d_in[3];
    const float* b2 = (const float*)d_in[4];
    float* out = (float*)d_out;

    float* hid_out = nullptr;
    if (out_size >= B_ * T_ * O_ + B_ * H_)
        hid_out = out + (size_t)B_ * T_ * O_;

    const int gemm_smem = STG_HALFS * 2 * 2;  // 110592 B
    static int attr_done = 0;
    if (!attr_done) {
        cudaFuncSetAttribute(hgemm3, cudaFuncAttributeMaxDynamicSharedMemorySize,
                             gemm_smem);
        attr_done = 1;
    }

    init_kernel<<<128, 256>>>();
    split_x_kernel<<<16384, 256>>>(x);
    split_w_kernel<<<3072, 256>>>(W1, W2);
    hgemm3<<<dim3(8, 256), 256, gemm_smem>>>(b1, nullptr, 512, 1);   // pre
    recurrence_cluster<<<16, 256>>>(W1, hid_out);
    hgemm3<<<dim3(8, 256), 256, gemm_smem>>>(b2, out, 1024, 0);      // post
}